// round 7
// baseline (speedup 1.0000x reference)
#include <cuda_runtime.h>
#include <cstdint>

#define N 2048
#define D 1024
#define GCE_Q 0.7f
#define EPS 1e-8f
#define INV_LN2 1.4426950408889634f
#define LN2 0.6931471805599453f
#define EPS2 (EPS * INV_LN2)

#define CP2 20   // interleaved exp row stride: 10 classes x 2 heads
#define CPS 13   // scalar raw row stride (odd -> conflict-free)

typedef unsigned long long ull;

// -------- device scratch (no allocations) --------
// All log-domain tables are stored in log2 units (divided by ln2).
__device__ __align__(16) float g_iEA2[N * CP2];  // i-side interleaved exp(v-m): [row][c][head]
__device__ __align__(16) float g_jEB2[N * CP2];  // j-side interleaved
__device__ float g_iAbpM[N * CPS];               // (Ab'[i,c] - mAb[i]) / ln2
__device__ __align__(16) float2 g_jCB[N * 10];   // ((mBc - Bc[j,c])/ln2, (mBb - Bb[j,c])/ln2)
__device__ float g_iacyM[N];                     // (Ac'[i,y[i]] - mAc[i]) / ln2
__device__ float g_iabyM[N];                     // (Ab'[i,y[i]] - mAb[i]) / ln2
__device__ float g_jbbyM[N];                     // (Bb[j,y[j]] - mBb[j]) / ln2

__device__ __forceinline__ void fma2(ull& acc, ull a, ull b) {
    asm("fma.rn.f32x2 %0, %1, %2, %0;" : "+l"(acc) : "l"(a), "l"(b));
}
__device__ __forceinline__ float f2lo(ull v) {
    return __uint_as_float((unsigned)(v & 0xffffffffull));
}
__device__ __forceinline__ float f2hi(ull v) {
    return __uint_as_float((unsigned)(v >> 32));
}
__device__ __forceinline__ float ex2f(float x) {
    float r;
    asm("ex2.approx.ftz.f32 %0, %1;" : "=f"(r) : "f"(x));
    return r;
}
__device__ __forceinline__ float lg2f(float x) {
    float r;
    asm("lg2.approx.ftz.f32 %0, %1;" : "=f"(r) : "f"(x));
    return r;
}

// ============================================================
// Kernel 1: logits + fused softmax stats (log2-domain tables).
// 512 blocks x 256 thr. Block: 8 virtual rows (one side), both
// heads. Warp w: head = w>>2, rows = base + (w&3)*2.
// ============================================================
__global__ void __launch_bounds__(256) logits_kernel(
    const float* __restrict__ zc, const float* __restrict__ zb,
    const float* __restrict__ Wc, const float* __restrict__ bc,
    const float* __restrict__ Wb, const float* __restrict__ bb,
    const int* __restrict__ y)
{
    __shared__ float slog[8][20];   // [block row][head*10+c], raw logits

    const int tid = threadIdx.x;
    const int w = tid >> 5, lane = tid & 31;
    const int head = w >> 2;
    const int rp = w & 3;
    const int vrb = blockIdx.x * 8;
    const int vr = vrb + rp * 2;
    const int side = vr >> 11;
    const int grow = vr & (N - 1);

    const ulonglong2* z2 = (const ulonglong2*)((side ? zb : zc) + (size_t)grow * D);
    const ulonglong2* w2 = (const ulonglong2*)(head ? Wb : Wc);

    ull acc0[10], acc1[10];
#pragma unroll
    for (int c = 0; c < 10; c++) { acc0[c] = 0ull; acc1[c] = 0ull; }

#pragma unroll
    for (int k = 0; k < 8; k++) {
        const int d = lane + 32 * k;
        const ulonglong2 za = z2[d];
        const ulonglong2 zbv = z2[256 + d];
#pragma unroll
        for (int c = 0; c < 10; c++) {
            const ulonglong2 wv = w2[c * 256 + d];
            fma2(acc0[c], za.x, wv.x);
            fma2(acc0[c], za.y, wv.y);
            fma2(acc1[c], zbv.x, wv.x);
            fma2(acc1[c], zbv.y, wv.y);
        }
    }

    float s0[10], s1[10];
#pragma unroll
    for (int c = 0; c < 10; c++) {
        s0[c] = f2lo(acc0[c]) + f2hi(acc0[c]);
        s1[c] = f2lo(acc1[c]) + f2hi(acc1[c]);
    }
#pragma unroll
    for (int off = 16; off > 0; off >>= 1) {
#pragma unroll
        for (int c = 0; c < 10; c++) {
            s0[c] += __shfl_down_sync(0xffffffffu, s0[c], off);
            s1[c] += __shfl_down_sync(0xffffffffu, s1[c], off);
        }
    }
    if (lane == 0) {
#pragma unroll
        for (int c = 0; c < 10; c++) {
            slog[rp * 2 + 0][head * 10 + c] = s0[c];
            slog[rp * 2 + 1][head * 10 + c] = s1[c];
        }
    }
    __syncthreads();

    if (tid < 8) {
        const int row = (vrb + tid) & (N - 1);
        float v[20];
#pragma unroll
        for (int k = 0; k < 20; k++) v[k] = slog[tid][k];
        if (side == 0) {
#pragma unroll
            for (int k = 0; k < 10; k++) { v[k] += bc[k]; v[10 + k] += bb[k]; }
        }
        // switch to log2 units
#pragma unroll
        for (int k = 0; k < 20; k++) v[k] *= INV_LN2;
        float mc = v[0], mb = v[10];
#pragma unroll
        for (int k = 1; k < 10; k++) {
            mc = fmaxf(mc, v[k]);
            mb = fmaxf(mb, v[10 + k]);
        }
        const int yr = y[row];
        if (side == 0) {
#pragma unroll
            for (int c = 0; c < 10; c++) {
                g_iEA2[row * CP2 + 2 * c]     = ex2f(v[c] - mc);
                g_iEA2[row * CP2 + 2 * c + 1] = ex2f(v[10 + c] - mb);
                g_iAbpM[row * CPS + c] = v[10 + c] - mb;
            }
            g_iacyM[row] = v[yr] - mc;
            g_iabyM[row] = v[10 + yr] - mb;
        } else {
#pragma unroll
            for (int c = 0; c < 10; c++) {
                g_jEB2[row * CP2 + 2 * c]     = ex2f(v[c] - mc);
                g_jEB2[row * CP2 + 2 * c + 1] = ex2f(v[10 + c] - mb);
                g_jCB[row * 10 + c] = make_float2(mc - v[c], mb - v[10 + c]);
            }
            g_jbbyM[row] = v[10 + yr] - mb;
        }
    }
}

// ============================================================
// Kernel 2: 64x64 tile / block, 256 threads, 4x4 per thread.
// j rows per thread = {tx, tx+16, tx+32, tx+48}: conflict-free LDS.
// Epilogue entirely in log2 domain: raw LG2/EX2/RCP, one final xLN2.
// ============================================================
__global__ void __launch_bounds__(256, 5) pair_kernel(
    const int* __restrict__ y, float* __restrict__ out)
{
    __shared__ __align__(16) float sEA2[64 * CP2];
    __shared__ __align__(16) float sEB2[64 * CP2];
    __shared__ __align__(16) ull   sCB[64 * 10];
    __shared__ float sAbpM[64 * CPS];
    __shared__ float sacyM[64], sabyM[64], sbbyM[64];
    __shared__ int   syi[64], syj[64];

    const int i0 = blockIdx.y * 64;
    const int j0 = blockIdx.x * 64;
    const int tid = threadIdx.x;

    for (int idx = tid; idx < 64 * (CP2 / 4); idx += 256) {
        ((float4*)sEA2)[idx] = ((const float4*)g_iEA2)[i0 * (CP2 / 4) + idx];
        ((float4*)sEB2)[idx] = ((const float4*)g_jEB2)[j0 * (CP2 / 4) + idx];
    }
    for (int idx = tid; idx < 64 * 5; idx += 256)
        ((float4*)sCB)[idx] = ((const float4*)g_jCB)[j0 * 5 + idx];
    for (int idx = tid; idx < 64 * CPS; idx += 256)
        sAbpM[idx] = g_iAbpM[i0 * CPS + idx];
    if (tid < 64) {
        sacyM[tid] = g_iacyM[i0 + tid];
        sabyM[tid] = g_iabyM[i0 + tid];
        syi[tid]   = y[i0 + tid];
    } else if (tid < 128) {
        const int u = tid - 64;
        sbbyM[u] = g_jbbyM[j0 + u];
        syj[u]   = y[j0 + u];
    }
    __syncthreads();

    const int tx = tid & 15;
    const int ty = tid >> 4;
    const int il = ty * 4;

    ull acc[4][4];
#pragma unroll
    for (int a = 0; a < 4; a++)
#pragma unroll
        for (int b = 0; b < 4; b++) acc[a][b] = 0ull;

#pragma unroll
    for (int g = 0; g < 5; g++) {
        ulonglong2 ea[4], eb[4];
#pragma unroll
        for (int a = 0; a < 4; a++)
            ea[a] = *(const ulonglong2*)&sEA2[(il + a) * CP2 + g * 4];
#pragma unroll
        for (int b = 0; b < 4; b++)
            eb[b] = *(const ulonglong2*)&sEB2[(tx + 16 * b) * CP2 + g * 4];
#pragma unroll
        for (int a = 0; a < 4; a++)
#pragma unroll
            for (int b = 0; b < 4; b++) {
                fma2(acc[a][b], ea[a].x, eb[b].x);
                fma2(acc[a][b], ea[a].y, eb[b].y);
            }
    }

    float acy[4], aby[4];
    int   yia[4];
#pragma unroll
    for (int a = 0; a < 4; a++) {
        acy[a] = sacyM[il + a];
        aby[a] = sabyM[il + a];
        yia[a] = syi[il + a];
    }
    float bby[4];
    int   yjb[4], jr[4];
#pragma unroll
    for (int b = 0; b < 4; b++) {
        jr[b]  = tx + 16 * b;
        bby[b] = sbbyM[jr[b]];
        yjb[b] = syj[jr[b]];
    }

#pragma unroll
    for (int a = 0; a < 4; a++) {
        float* orow = out + (size_t)(i0 + il + a) * N + j0;
#pragma unroll
        for (int b = 0; b < 4; b++) {
            const float lc2 = lg2f(f2lo(acc[a][b]));
            const float lb2 = lg2f(f2hi(acc[a][b]));
            const ull  cb = sCB[jr[b] * 10 + yia[a]];
            const float ce_pc2 = lc2 - acy[a] + f2lo(cb);
            const float ce_pb2 = lb2 - aby[a] + f2hi(cb);
            const float logp2  = sAbpM[(il + a) * CPS + yjb[b]] + bby[b] - lb2;
            const float gce2   = -logp2 * ex2f(GCE_Q * logp2);
            const float wr = __fdividef(ce_pb2, ce_pc2 + ce_pb2 + EPS2);
            orow[jr[b]] = fmaf(wr, ce_pc2 - gce2, gce2) * LN2;
        }
    }
}

// ============================================================
extern "C" void kernel_launch(void* const* d_in, const int* in_sizes, int n_in,
                              void* d_out, int out_size)
{
    const float* zc = (const float*)d_in[0];  // [N, D]
    const float* zb = (const float*)d_in[1];  // [N, D]
    const float* Wc = (const float*)d_in[2];  // [C, D]
    const float* bc = (const float*)d_in[3];  // [C]
    const float* Wb = (const float*)d_in[4];  // [C, D]
    const float* bb = (const float*)d_in[5];  // [C]
    const int*   y  = (const int*)d_in[6];    // [N]
    float* out = (float*)d_out;               // [N, N]

    logits_kernel<<<(2 * N) / 8, 256>>>(zc, zb, Wc, bc, Wb, bb, y);

    dim3 g2(N / 64, N / 64);
    pair_kernel<<<g2, 256>>>(y, out);
}

// round 9
// speedup vs baseline: 1.2685x; 1.2685x over previous
#include <cuda_runtime.h>
#include <cstdint>

#define N 2048
#define D 1024
#define GCE_Q 0.7f
#define EPS 1e-8f
#define INV_LN2 1.4426950408889634f
#define LN2 0.6931471805599453f
#define EPS2 (EPS * INV_LN2)

#define CP2 20   // interleaved exp row stride: 10 classes x 2 heads
#define CPS 13   // scalar raw row stride (odd -> conflict-free)

typedef unsigned long long ull;

// -------- device scratch (no allocations) --------
// All log-domain tables stored in log2 units (divided by ln2).
__device__ __align__(16) float g_iEA2[N * CP2];  // i-side interleaved exp(v-m): [row][c][head]
__device__ __align__(16) float g_jEB2[N * CP2];  // j-side interleaved
__device__ float g_iAbpM[N * CPS];               // (Ab'[i,c] - mAb[i]) / ln2
__device__ __align__(16) float2 g_jCB[N * 10];   // ((mBc - Bc[j,c])/ln2, (mBb - Bb[j,c])/ln2)
__device__ float g_iacyM[N];                     // (Ac'[i,y[i]] - mAc[i]) / ln2
__device__ float g_iabyM[N];                     // (Ab'[i,y[i]] - mAb[i]) / ln2
__device__ float g_jbbyM[N];                     // (Bb[j,y[j]] - mBb[j]) / ln2

__device__ __forceinline__ void fma2(ull& acc, ull a, ull b) {
    asm("fma.rn.f32x2 %0, %1, %2, %0;" : "+l"(acc) : "l"(a), "l"(b));
}
__device__ __forceinline__ float f2lo(ull v) {
    return __uint_as_float((unsigned)(v & 0xffffffffull));
}
__device__ __forceinline__ float f2hi(ull v) {
    return __uint_as_float((unsigned)(v >> 32));
}
__device__ __forceinline__ float ex2f(float x) {
    float r;
    asm("ex2.approx.ftz.f32 %0, %1;" : "=f"(r) : "f"(x));
    return r;
}
__device__ __forceinline__ float lg2f(float x) {
    float r;
    asm("lg2.approx.ftz.f32 %0, %1;" : "=f"(r) : "f"(x));
    return r;
}

// ============================================================
// Kernel 1: logits + fused softmax stats (log2-domain tables).
// 1024 blocks x 128 thr. Block: 4 virtual rows (one side), both
// heads. Warp w: head = w>>1, row-pair = w&1.
// ============================================================
__global__ void __launch_bounds__(128) logits_kernel(
    const float* __restrict__ zc, const float* __restrict__ zb,
    const float* __restrict__ Wc, const float* __restrict__ bc,
    const float* __restrict__ Wb, const float* __restrict__ bb,
    const int* __restrict__ y)
{
    __shared__ float slog[4][20];   // [block row][head*10+c], raw logits

    const int tid = threadIdx.x;
    const int w = tid >> 5, lane = tid & 31;
    const int head = w >> 1;
    const int rp = w & 1;
    const int vrb = blockIdx.x * 4;
    const int vr = vrb + rp * 2;
    const int side = vr >> 11;
    const int grow = vr & (N - 1);

    const ulonglong2* z2 = (const ulonglong2*)((side ? zb : zc) + (size_t)grow * D);
    const ulonglong2* w2 = (const ulonglong2*)(head ? Wb : Wc);

    ull acc0[10], acc1[10];
#pragma unroll
    for (int c = 0; c < 10; c++) { acc0[c] = 0ull; acc1[c] = 0ull; }

#pragma unroll
    for (int k = 0; k < 8; k++) {
        const int d = lane + 32 * k;          // 16B units, 256 per row
        const ulonglong2 za = z2[d];
        const ulonglong2 zbv = z2[256 + d];
#pragma unroll
        for (int c = 0; c < 10; c++) {
            const ulonglong2 wv = w2[c * 256 + d];
            fma2(acc0[c], za.x, wv.x);
            fma2(acc0[c], za.y, wv.y);
            fma2(acc1[c], zbv.x, wv.x);
            fma2(acc1[c], zbv.y, wv.y);
        }
    }

    float s0[10], s1[10];
#pragma unroll
    for (int c = 0; c < 10; c++) {
        s0[c] = f2lo(acc0[c]) + f2hi(acc0[c]);
        s1[c] = f2lo(acc1[c]) + f2hi(acc1[c]);
    }
#pragma unroll
    for (int off = 16; off > 0; off >>= 1) {
#pragma unroll
        for (int c = 0; c < 10; c++) {
            s0[c] += __shfl_down_sync(0xffffffffu, s0[c], off);
            s1[c] += __shfl_down_sync(0xffffffffu, s1[c], off);
        }
    }
    if (lane == 0) {
#pragma unroll
        for (int c = 0; c < 10; c++) {
            slog[rp * 2 + 0][head * 10 + c] = s0[c];
            slog[rp * 2 + 1][head * 10 + c] = s1[c];
        }
    }
    __syncthreads();

    if (tid < 4) {
        const int row = (vrb + tid) & (N - 1);
        float v[20];
#pragma unroll
        for (int k = 0; k < 20; k++) v[k] = slog[tid][k];
        if (side == 0) {
#pragma unroll
            for (int k = 0; k < 10; k++) { v[k] += bc[k]; v[10 + k] += bb[k]; }
        }
        // switch to log2 units
#pragma unroll
        for (int k = 0; k < 20; k++) v[k] *= INV_LN2;
        float mc = v[0], mb = v[10];
#pragma unroll
        for (int k = 1; k < 10; k++) {
            mc = fmaxf(mc, v[k]);
            mb = fmaxf(mb, v[10 + k]);
        }
        const int yr = y[row];
        if (side == 0) {
#pragma unroll
            for (int c = 0; c < 10; c++) {
                g_iEA2[row * CP2 + 2 * c]     = ex2f(v[c] - mc);
                g_iEA2[row * CP2 + 2 * c + 1] = ex2f(v[10 + c] - mb);
                g_iAbpM[row * CPS + c] = v[10 + c] - mb;
            }
            g_iacyM[row] = v[yr] - mc;
            g_iabyM[row] = v[10 + yr] - mb;
        } else {
#pragma unroll
            for (int c = 0; c < 10; c++) {
                g_jEB2[row * CP2 + 2 * c]     = ex2f(v[c] - mc);
                g_jEB2[row * CP2 + 2 * c + 1] = ex2f(v[10 + c] - mb);
                g_jCB[row * 10 + c] = make_float2(mc - v[c], mb - v[10 + c]);
            }
            g_jbbyM[row] = v[10 + yr] - mb;
        }
    }
}

// ============================================================
// Kernel 2: 64x64 tile / block, 256 threads, 4x4 per thread.
// j rows per thread = {tx, tx+16, tx+32, tx+48}: conflict-free LDS.
// Epilogue entirely in log2 domain. 4 blocks/SM (no spills).
// ============================================================
__global__ void __launch_bounds__(256, 4) pair_kernel(
    const int* __restrict__ y, float* __restrict__ out)
{
    __shared__ __align__(16) float sEA2[64 * CP2];
    __shared__ __align__(16) float sEB2[64 * CP2];
    __shared__ __align__(16) ull   sCB[64 * 10];
    __shared__ float sAbpM[64 * CPS];
    __shared__ float sacyM[64], sabyM[64], sbbyM[64];
    __shared__ int   syi[64], syj[64];

    const int i0 = blockIdx.y * 64;
    const int j0 = blockIdx.x * 64;
    const int tid = threadIdx.x;

    for (int idx = tid; idx < 64 * (CP2 / 4); idx += 256) {
        ((float4*)sEA2)[idx] = ((const float4*)g_iEA2)[i0 * (CP2 / 4) + idx];
        ((float4*)sEB2)[idx] = ((const float4*)g_jEB2)[j0 * (CP2 / 4) + idx];
    }
    for (int idx = tid; idx < 64 * 5; idx += 256)
        ((float4*)sCB)[idx] = ((const float4*)g_jCB)[j0 * 5 + idx];
    for (int idx = tid; idx < 64 * CPS; idx += 256)
        sAbpM[idx] = g_iAbpM[i0 * CPS + idx];
    if (tid < 64) {
        sacyM[tid] = g_iacyM[i0 + tid];
        sabyM[tid] = g_iabyM[i0 + tid];
        syi[tid]   = y[i0 + tid];
    } else if (tid < 128) {
        const int u = tid - 64;
        sbbyM[u] = g_jbbyM[j0 + u];
        syj[u]   = y[j0 + u];
    }
    __syncthreads();

    const int tx = tid & 15;
    const int ty = tid >> 4;
    const int il = ty * 4;

    ull acc[4][4];
#pragma unroll
    for (int a = 0; a < 4; a++)
#pragma unroll
        for (int b = 0; b < 4; b++) acc[a][b] = 0ull;

#pragma unroll
    for (int g = 0; g < 5; g++) {
        ulonglong2 ea[4], eb[4];
#pragma unroll
        for (int a = 0; a < 4; a++)
            ea[a] = *(const ulonglong2*)&sEA2[(il + a) * CP2 + g * 4];
#pragma unroll
        for (int b = 0; b < 4; b++)
            eb[b] = *(const ulonglong2*)&sEB2[(tx + 16 * b) * CP2 + g * 4];
#pragma unroll
        for (int a = 0; a < 4; a++)
#pragma unroll
            for (int b = 0; b < 4; b++) {
                fma2(acc[a][b], ea[a].x, eb[b].x);
                fma2(acc[a][b], ea[a].y, eb[b].y);
            }
    }

    float acy[4], aby[4];
    int   yia[4];
#pragma unroll
    for (int a = 0; a < 4; a++) {
        acy[a] = sacyM[il + a];
        aby[a] = sabyM[il + a];
        yia[a] = syi[il + a];
    }
    float bby[4];
    int   yjb[4], jr[4];
#pragma unroll
    for (int b = 0; b < 4; b++) {
        jr[b]  = tx + 16 * b;
        bby[b] = sbbyM[jr[b]];
        yjb[b] = syj[jr[b]];
    }

#pragma unroll
    for (int a = 0; a < 4; a++) {
        float* orow = out + (size_t)(i0 + il + a) * N + j0;
#pragma unroll
        for (int b = 0; b < 4; b++) {
            const float lc2 = lg2f(f2lo(acc[a][b]));
            const float lb2 = lg2f(f2hi(acc[a][b]));
            const ull  cb = sCB[jr[b] * 10 + yia[a]];
            const float ce_pc2 = lc2 - acy[a] + f2lo(cb);
            const float ce_pb2 = lb2 - aby[a] + f2hi(cb);
            const float logp2  = sAbpM[(il + a) * CPS + yjb[b]] + bby[b] - lb2;
            const float gce2   = -logp2 * ex2f(GCE_Q * logp2);
            const float wr = __fdividef(ce_pb2, ce_pc2 + ce_pb2 + EPS2);
            orow[jr[b]] = fmaf(wr, ce_pc2 - gce2, gce2) * LN2;
        }
    }
}

// ============================================================
extern "C" void kernel_launch(void* const* d_in, const int* in_sizes, int n_in,
                              void* d_out, int out_size)
{
    const float* zc = (const float*)d_in[0];  // [N, D]
    const float* zb = (const float*)d_in[1];  // [N, D]
    const float* Wc = (const float*)d_in[2];  // [C, D]
    const float* bc = (const float*)d_in[3];  // [C]
    const float* Wb = (const float*)d_in[4];  // [C, D]
    const float* bb = (const float*)d_in[5];  // [C]
    const int*   y  = (const int*)d_in[6];    // [N]
    float* out = (float*)d_out;               // [N, N]

    logits_kernel<<<(2 * N) / 4, 128>>>(zc, zb, Wc, bc, Wb, bb, y);

    dim3 g2(N / 64, N / 64);
    pair_kernel<<<g2, 256>>>(y, out);
}

// round 10
// speedup vs baseline: 1.4866x; 1.1720x over previous
#include <cuda_runtime.h>
#include <cstdint>

#define N 2048
#define D 1024
#define GCE_Q 0.7f
#define EPS 1e-8f
#define INV_LN2 1.4426950408889634f
#define LN2 0.6931471805599453f
#define EPS2 (EPS * INV_LN2)

#define CP2 20   // interleaved exp row stride: 10 classes x 2 heads
#define CPS 13   // scalar raw row stride (odd -> conflict-free)

typedef unsigned long long ull;

// -------- device scratch (no allocations) --------
// All log-domain tables stored in log2 units (divided by ln2).
__device__ __align__(16) float g_iEA2[N * CP2];  // i-side interleaved exp(v-m): [row][c][head]
__device__ __align__(16) float g_jEB2[N * CP2];  // j-side interleaved
__device__ float g_iAbpM[N * CPS];               // (Ab'[i,c] - mAb[i]) / ln2
__device__ __align__(16) float2 g_jCB[N * 10];   // ((mBc - Bc[j,c])/ln2, (mBb - Bb[j,c])/ln2)
__device__ float g_iacyM[N];                     // (Ac'[i,y[i]] - mAc[i]) / ln2
__device__ float g_iabyM[N];                     // (Ab'[i,y[i]] - mAb[i]) / ln2
__device__ float g_jbbyM[N];                     // (Bb[j,y[j]] - mBb[j]) / ln2

__device__ __forceinline__ void fma2(ull& acc, ull a, ull b) {
    asm("fma.rn.f32x2 %0, %1, %2, %0;" : "+l"(acc) : "l"(a), "l"(b));
}
__device__ __forceinline__ float f2lo(ull v) {
    return __uint_as_float((unsigned)(v & 0xffffffffull));
}
__device__ __forceinline__ float f2hi(ull v) {
    return __uint_as_float((unsigned)(v >> 32));
}
__device__ __forceinline__ float ex2f(float x) {
    float r;
    asm("ex2.approx.ftz.f32 %0, %1;" : "=f"(r) : "f"(x));
    return r;
}
__device__ __forceinline__ float lg2f(float x) {
    float r;
    asm("lg2.approx.ftz.f32 %0, %1;" : "=f"(r) : "f"(x));
    return r;
}

// ============================================================
// Kernel 1 (R3 structure, best measured): 8 rows/block, 128 thr.
// Thread owns one float4 column; W amortized over 8 rows in regs
// (acc[8][10]); stride-85 smem matrix reduce; log2-domain tail.
// Virtual rows [0,2048)=z_c side, [2048,4096)=z_b side.
// ============================================================
#define K1_ROWS 8
#define K1_THR 128
#define RSTR 85

__global__ void __launch_bounds__(K1_THR) rowstats_kernel(
    const float* __restrict__ zc, const float* __restrict__ zb,
    const float* __restrict__ Wc, const float* __restrict__ bc,
    const float* __restrict__ Wb, const float* __restrict__ bb,
    const int* __restrict__ y)
{
    __shared__ float red[K1_THR * RSTR];     // 43.5 KB partials
    __shared__ float vals[K1_ROWS][20];      // reduced raw logits

    const int t = threadIdx.x;
    const int vr0 = blockIdx.x * K1_ROWS;
    const int side = vr0 >> 11;              // 0 -> z_c (A side), 1 -> z_b (B side)
    const int grow0 = vr0 & (N - 1);

    const float4* z4 = (const float4*)((side ? zb : zc) + (size_t)grow0 * D);

    for (int h = 0; h < 2; h++) {
        const float4* w4 = (const float4*)(h ? Wb : Wc);
        float acc[K1_ROWS][10];
#pragma unroll
        for (int r = 0; r < K1_ROWS; r++)
#pragma unroll
            for (int c = 0; c < 10; c++) acc[r][c] = 0.f;

#pragma unroll
        for (int kk = 0; kk < 2; kk++) {
            const int d4 = t + kk * K1_THR;   // 256 float4 per row
            float4 zv[K1_ROWS];
#pragma unroll
            for (int r = 0; r < K1_ROWS; r++) zv[r] = z4[r * 256 + d4];
#pragma unroll
            for (int c = 0; c < 10; c++) {
                const float4 wv = w4[c * 256 + d4];
#pragma unroll
                for (int r = 0; r < K1_ROWS; r++) {
                    acc[r][c] = fmaf(zv[r].x, wv.x,
                                fmaf(zv[r].y, wv.y,
                                fmaf(zv[r].z, wv.z,
                                fmaf(zv[r].w, wv.w, acc[r][c]))));
                }
            }
        }

        // dump partials (stride 85: conflict-free write and read)
#pragma unroll
        for (int r = 0; r < K1_ROWS; r++)
#pragma unroll
            for (int c = 0; c < 10; c++)
                red[t * RSTR + r * 10 + c] = acc[r][c];
        __syncthreads();

        if (t < 80) {
            float s0 = 0.f, s1 = 0.f, s2 = 0.f, s3 = 0.f;
#pragma unroll 8
            for (int u = 0; u < K1_THR; u += 4) {
                s0 += red[(u + 0) * RSTR + t];
                s1 += red[(u + 1) * RSTR + t];
                s2 += red[(u + 2) * RSTR + t];
                s3 += red[(u + 3) * RSTR + t];
            }
            vals[t / 10][h * 10 + t % 10] = (s0 + s1) + (s2 + s3);
        }
        __syncthreads();   // before h=1 overwrites red / before tail
    }

    // log2-domain softmax tail: one thread per block row
    if (t < K1_ROWS) {
        const int row = grow0 + t;
        float v[20];
#pragma unroll
        for (int k = 0; k < 20; k++) v[k] = vals[t][k];
        if (side == 0) {
#pragma unroll
            for (int k = 0; k < 10; k++) { v[k] += bc[k]; v[10 + k] += bb[k]; }
        }
#pragma unroll
        for (int k = 0; k < 20; k++) v[k] *= INV_LN2;   // log2 units
        float mc = v[0], mb = v[10];
#pragma unroll
        for (int k = 1; k < 10; k++) {
            mc = fmaxf(mc, v[k]);
            mb = fmaxf(mb, v[10 + k]);
        }
        const int yr = y[row];
        if (side == 0) {
#pragma unroll
            for (int c = 0; c < 10; c++) {
                g_iEA2[row * CP2 + 2 * c]     = ex2f(v[c] - mc);
                g_iEA2[row * CP2 + 2 * c + 1] = ex2f(v[10 + c] - mb);
                g_iAbpM[row * CPS + c] = v[10 + c] - mb;
            }
            g_iacyM[row] = v[yr] - mc;
            g_iabyM[row] = v[10 + yr] - mb;
        } else {
#pragma unroll
            for (int c = 0; c < 10; c++) {
                g_jEB2[row * CP2 + 2 * c]     = ex2f(v[c] - mc);
                g_jEB2[row * CP2 + 2 * c + 1] = ex2f(v[10 + c] - mb);
                g_jCB[row * 10 + c] = make_float2(mc - v[c], mb - v[10 + c]);
            }
            g_jbbyM[row] = v[10 + yr] - mb;
        }
    }
}

// ============================================================
// Kernel 2 (unchanged from R9, best measured 17.06us):
// 64x64 tile / block, 256 threads, 4x4 per thread.
// j rows per thread = {tx, tx+16, tx+32, tx+48}: conflict-free LDS.
// Epilogue entirely in log2 domain. 4 blocks/SM (no spills).
// ============================================================
__global__ void __launch_bounds__(256, 4) pair_kernel(
    const int* __restrict__ y, float* __restrict__ out)
{
    __shared__ __align__(16) float sEA2[64 * CP2];
    __shared__ __align__(16) float sEB2[64 * CP2];
    __shared__ __align__(16) ull   sCB[64 * 10];
    __shared__ float sAbpM[64 * CPS];
    __shared__ float sacyM[64], sabyM[64], sbbyM[64];
    __shared__ int   syi[64], syj[64];

    const int i0 = blockIdx.y * 64;
    const int j0 = blockIdx.x * 64;
    const int tid = threadIdx.x;

    for (int idx = tid; idx < 64 * (CP2 / 4); idx += 256) {
        ((float4*)sEA2)[idx] = ((const float4*)g_iEA2)[i0 * (CP2 / 4) + idx];
        ((float4*)sEB2)[idx] = ((const float4*)g_jEB2)[j0 * (CP2 / 4) + idx];
    }
    for (int idx = tid; idx < 64 * 5; idx += 256)
        ((float4*)sCB)[idx] = ((const float4*)g_jCB)[j0 * 5 + idx];
    for (int idx = tid; idx < 64 * CPS; idx += 256)
        sAbpM[idx] = g_iAbpM[i0 * CPS + idx];
    if (tid < 64) {
        sacyM[tid] = g_iacyM[i0 + tid];
        sabyM[tid] = g_iabyM[i0 + tid];
        syi[tid]   = y[i0 + tid];
    } else if (tid < 128) {
        const int u = tid - 64;
        sbbyM[u] = g_jbbyM[j0 + u];
        syj[u]   = y[j0 + u];
    }
    __syncthreads();

    const int tx = tid & 15;
    const int ty = tid >> 4;
    const int il = ty * 4;

    ull acc[4][4];
#pragma unroll
    for (int a = 0; a < 4; a++)
#pragma unroll
        for (int b = 0; b < 4; b++) acc[a][b] = 0ull;

#pragma unroll
    for (int g = 0; g < 5; g++) {
        ulonglong2 ea[4], eb[4];
#pragma unroll
        for (int a = 0; a < 4; a++)
            ea[a] = *(const ulonglong2*)&sEA2[(il + a) * CP2 + g * 4];
#pragma unroll
        for (int b = 0; b < 4; b++)
            eb[b] = *(const ulonglong2*)&sEB2[(tx + 16 * b) * CP2 + g * 4];
#pragma unroll
        for (int a = 0; a < 4; a++)
#pragma unroll
            for (int b = 0; b < 4; b++) {
                fma2(acc[a][b], ea[a].x, eb[b].x);
                fma2(acc[a][b], ea[a].y, eb[b].y);
            }
    }

    float acy[4], aby[4];
    int   yia[4];
#pragma unroll
    for (int a = 0; a < 4; a++) {
        acy[a] = sacyM[il + a];
        aby[a] = sabyM[il + a];
        yia[a] = syi[il + a];
    }
    float bby[4];
    int   yjb[4], jr[4];
#pragma unroll
    for (int b = 0; b < 4; b++) {
        jr[b]  = tx + 16 * b;
        bby[b] = sbbyM[jr[b]];
        yjb[b] = syj[jr[b]];
    }

#pragma unroll
    for (int a = 0; a < 4; a++) {
        float* orow = out + (size_t)(i0 + il + a) * N + j0;
#pragma unroll
        for (int b = 0; b < 4; b++) {
            const float lc2 = lg2f(f2lo(acc[a][b]));
            const float lb2 = lg2f(f2hi(acc[a][b]));
            const ull  cb = sCB[jr[b] * 10 + yia[a]];
            const float ce_pc2 = lc2 - acy[a] + f2lo(cb);
            const float ce_pb2 = lb2 - aby[a] + f2hi(cb);
            const float logp2  = sAbpM[(il + a) * CPS + yjb[b]] + bby[b] - lb2;
            const float gce2   = -logp2 * ex2f(GCE_Q * logp2);
            const float wr = __fdividef(ce_pb2, ce_pc2 + ce_pb2 + EPS2);
            orow[jr[b]] = fmaf(wr, ce_pc2 - gce2, gce2) * LN2;
        }
    }
}

// ============================================================
extern "C" void kernel_launch(void* const* d_in, const int* in_sizes, int n_in,
                              void* d_out, int out_size)
{
    const float* zc = (const float*)d_in[0];  // [N, D]
    const float* zb = (const float*)d_in[1];  // [N, D]
    const float* Wc = (const float*)d_in[2];  // [C, D]
    const float* bc = (const float*)d_in[3];  // [C]
    const float* Wb = (const float*)d_in[4];  // [C, D]
    const float* bb = (const float*)d_in[5];  // [C]
    const int*   y  = (const int*)d_in[6];    // [N]
    float* out = (float*)d_out;               // [N, N]

    rowstats_kernel<<<(2 * N) / K1_ROWS, K1_THR>>>(zc, zb, Wc, bc, Wb, bb, y);

    dim3 g2(N / 64, N / 64);
    pair_kernel<<<g2, 256>>>(y, out);
}